// round 9
// baseline (speedup 1.0000x reference)
#include <cuda_runtime.h>

#define Bc   4
#define Hc   512
#define Wc   229
#define Cc   32
#define OUTc 88
#define WTP  96                      /* padded weight out-stride */
#define FRAME_ELEMS (Bc*Hc*OUTc)     /* 180224 */
#define NROW (Bc*Hc)                 /* 2048 */
#define RPB  8                       /* rows per block */
#define NBLK (NROW/RPB)              /* 256 blocks */
#define HOW  232                     /* halo/ov row stride */

__device__ float g_wT96[Wc*WTP];      // folded weights, transposed [w][o], o-pad 96 (zero-init)
__device__ int   g_done;              // weff columns published (monotonic across replays)

// ---------------------------------------------------------------------------
// fast exp(d), d <= 0 : FMA-pipe exp2 poly + magic-number round
// ---------------------------------------------------------------------------
__device__ __forceinline__ float fexp_neg(float d)
{
    const float L2E   = 1.4426950408889634f;
    const float MAGIC = 12582912.0f;              // 1.5 * 2^23
    float t0 = fmaf(d, L2E, MAGIC);
    float r  = t0 - MAGIC;
    float f  = fmaf(d, L2E, -r);                  // f in [-0.5, 0.5]
    float p = 1.3333558146e-3f;
    p = fmaf(p, f, 9.6181291076e-3f);
    p = fmaf(p, f, 5.5504108665e-2f);
    p = fmaf(p, f, 2.4022650696e-1f);
    p = fmaf(p, f, 6.9314718056e-1f);
    p = fmaf(p, f, 1.0f);
    int ri = __float_as_int(t0) - 0x4B400000;
    ri = ri < -126 ? -126 : ri;
    return p * __int_as_float((ri + 127) << 23);
}

// ---------------------------------------------------------------------------
// Fully fused kernel. Block = 8 consecutive h-rows of one batch.
//   phase 0: blocks 0..87 fold one WeffT column -> g_wT96, bump g_done
//   phase 1: 8 softmax rows (attn out, ov -> smem)
//   phase 2: spin until g_done >= 88 (first-wave blocks 0..87 never wait)
//   phase 3: GEMM 8x88x229 with Weff staged per K-chunk + sigmoid epilogue
// ---------------------------------------------------------------------------
__global__ void __launch_bounds__(256)
fused(const float* __restrict__ spec,
      const float* __restrict__ Wq,  const float* __restrict__ Wk,
      const float* __restrict__ Wv,  const float* __restrict__ rel_t,
      const float* __restrict__ rel_f, const float* __restrict__ W_lin,
      const float* __restrict__ b_lin,
      float* __restrict__ out_frame, float* __restrict__ out_attn)
{
    __shared__ __align__(16) float s_h[10*HOW];     // 10 halo rows  (2320 f)
    __shared__ __align__(16) float s_ov[RPB*HOW];   // ov rows       (1856 f)
    __shared__ __align__(16) float s_attn[Wc*9];    // attn stage    (2061 f)
    __shared__ __align__(16) float s_wf[58*WTP];    // weff K-chunk  (5568 f)
    __shared__ float s_scal[7];

    int t   = threadIdx.x;
    int blk = blockIdx.x;
    int b   = blk >> 6;                      // batch
    int ho  = blk & 63;                      // h-octet

    // ---- scalars (A, Rt, Rf) per block ----
    if (t < 7) {
        if (t == 0) {
            float a = 0.f;
            #pragma unroll
            for (int c = 0; c < Cc; c++) a = fmaf(Wq[c], Wk[c], a);
            s_scal[0] = a;
        } else if (t <= 3) {
            int kt = t - 1; float r = 0.f;
            #pragma unroll
            for (int c = 0; c < 16; c++) r = fmaf(Wq[c], rel_t[c*3 + kt], r);
            s_scal[t] = r;
        } else {
            int kf = t - 4; float r = 0.f;
            #pragma unroll
            for (int c = 0; c < 16; c++) r = fmaf(Wq[16 + c], rel_f[c*3 + kf], r);
            s_scal[t] = r;
        }
    }

    // ---- phase 0: Weff fold (blocks 0..87) ----
    if (blk < OUTc) {
        if (t < Wc) {
            const float* base = W_lin + blk*(Cc*Wc) + t;
            float acc = 0.f;
            #pragma unroll
            for (int c = 0; c < Cc; c++)
                acc = fmaf(base[c*Wc], Wv[c], acc);
            g_wT96[t*WTP + blk] = acc;
        }
        __syncthreads();
        if (t == 0) { __threadfence(); atomicAdd(&g_done, 1); }
    }

    // ---- halo load: rows ho*8-1 .. ho*8+8 ----
    for (int i = t; i < 10*HOW; i += 256) {
        int j  = i / HOW;                    // halo row 0..9
        int cc = i - j*HOW;                  // 0..231
        int w  = cc - 1;
        int gh = ho*8 - 1 + j;
        float v = 0.f;
        if (gh >= 0 && gh < Hc && w >= 0 && w < Wc)
            v = spec[(b*Hc + gh)*Wc + w];
        s_h[j*HOW + cc] = v;
    }
    __syncthreads();

    // ---- phase 1: 8 softmax rows ----
    const float A = s_scal[0];
    const float Rt0 = s_scal[1], Rt1 = s_scal[2], Rt2 = s_scal[3];
    const float Rf0 = s_scal[4], Rf1 = s_scal[5], Rf2 = s_scal[6];

    for (int r = 0; r < RPB; r++) {
        if (t < Wc) {
            const float* h0 = s_h + (r    )*HOW + t;   // [t..t+2] = w-1..w+1
            const float* h1 = s_h + (r + 1)*HOW + t;
            const float* h2 = s_h + (r + 2)*HOW + t;
            float s  = h1[1];
            float sA = s * A;

            float nb[9], e[9];
            nb[0]=h0[0]; nb[1]=h0[1]; nb[2]=h0[2];
            nb[3]=h1[0]; nb[4]=h1[1]; nb[5]=h1[2];
            nb[6]=h2[0]; nb[7]=h2[1]; nb[8]=h2[2];
            float sr0 = s*Rt0, sr1 = s*Rt1, sr2 = s*Rt2;
            float sf0 = s*Rf0, sf1 = s*Rf1, sf2 = s*Rf2;
            e[0]=fmaf(sA,nb[0],sr0+sf0); e[1]=fmaf(sA,nb[1],sr0+sf1); e[2]=fmaf(sA,nb[2],sr0+sf2);
            e[3]=fmaf(sA,nb[3],sr1+sf0); e[4]=fmaf(sA,nb[4],sr1+sf1); e[5]=fmaf(sA,nb[5],sr1+sf2);
            e[6]=fmaf(sA,nb[6],sr2+sf0); e[7]=fmaf(sA,nb[7],sr2+sf1); e[8]=fmaf(sA,nb[8],sr2+sf2);

            float m = e[0];
            #pragma unroll
            for (int k = 1; k < 9; k++) m = fmaxf(m, e[k]);
            float p[9], sum = 0.f;
            #pragma unroll
            for (int k = 0; k < 9; k++) { p[k] = fexp_neg(e[k] - m); sum += p[k]; }
            float rinv = __fdividef(1.f, sum);

            float ov = 0.f;
            #pragma unroll
            for (int k = 0; k < 9; k++) {
                float a = p[k] * rinv;
                s_attn[t*9 + k] = a;
                ov = fmaf(a, nb[k], ov);
            }
            s_ov[r*HOW + t] = ov;
        }
        __syncthreads();
        {   // coalesced attn writeback for this row
            float* dst = out_attn + (b*Hc + ho*8 + r) * (Wc*9);
            for (int i = t; i < Wc*9; i += 256)
                dst[i] = s_attn[i];
        }
        __syncthreads();
    }

    // ---- phase 2: wait for all Weff columns ----
    if (t == 0) {
        while (*(volatile int*)&g_done < OUTc) { }
    }
    __syncthreads();

    // ---- phase 3: GEMM 8 rows x 88 outs x 229 K ----
    int r  = t / 22;                          // 0..7   (t<176 active)
    int og = t - r*22;                        // 0..21
    bool active = t < 176;
    float4 acc = {0.f, 0.f, 0.f, 0.f};

    const int w0s[5] = {0, 57, 114, 171, 229};
    #pragma unroll
    for (int ck = 0; ck < 4; ck++) {
        int w0  = w0s[ck];
        int len = w0s[ck+1] - w0;
        // stage weff chunk: contiguous copy (row stride == WTP)
        {
            const float4* src = (const float4*)(g_wT96 + w0*WTP);
            int n4 = (len*WTP) >> 2;
            for (int i = t; i < n4; i += 256)
                ((float4*)s_wf)[i] = src[i];
        }
        __syncthreads();
        if (active) {
            const float* ovr = s_ov + r*HOW + w0;
            const float* wvp = s_wf + og*4;
            int wl = 0;
            for (; wl + 2 <= len; wl += 2) {
                float  a0  = ovr[wl];
                float4 wv0 = *(const float4*)(wvp + (wl  )*WTP);
                float  a1  = ovr[wl + 1];
                float4 wv1 = *(const float4*)(wvp + (wl+1)*WTP);
                acc.x = fmaf(a0, wv0.x, acc.x); acc.y = fmaf(a0, wv0.y, acc.y);
                acc.z = fmaf(a0, wv0.z, acc.z); acc.w = fmaf(a0, wv0.w, acc.w);
                acc.x = fmaf(a1, wv1.x, acc.x); acc.y = fmaf(a1, wv1.y, acc.y);
                acc.z = fmaf(a1, wv1.z, acc.z); acc.w = fmaf(a1, wv1.w, acc.w);
            }
            for (; wl < len; wl++) {
                float  a  = ovr[wl];
                float4 wv = *(const float4*)(wvp + wl*WTP);
                acc.x = fmaf(a, wv.x, acc.x); acc.y = fmaf(a, wv.y, acc.y);
                acc.z = fmaf(a, wv.z, acc.z); acc.w = fmaf(a, wv.w, acc.w);
            }
        }
        __syncthreads();
    }

    if (active) {
        float4 bb = *(const float4*)&b_lin[og*4];
        float4 rr;
        rr.x = __fdividef(1.f, 1.f + __expf(-(acc.x + bb.x)));
        rr.y = __fdividef(1.f, 1.f + __expf(-(acc.y + bb.y)));
        rr.z = __fdividef(1.f, 1.f + __expf(-(acc.z + bb.z)));
        rr.w = __fdividef(1.f, 1.f + __expf(-(acc.w + bb.w)));
        int grow = b*Hc + ho*8 + r;
        *(float4*)&out_frame[grow*OUTc + og*4] = rr;
    }
}

// ---------------------------------------------------------------------------
extern "C" void kernel_launch(void* const* d_in, const int* in_sizes, int n_in,
                              void* d_out, int out_size)
{
    const float* spec  = (const float*)d_in[0];
    const float* Wq    = (const float*)d_in[1];
    const float* Wk    = (const float*)d_in[2];
    const float* Wv    = (const float*)d_in[3];
    const float* rel_t = (const float*)d_in[4];
    const float* rel_f = (const float*)d_in[5];
    const float* W_lin = (const float*)d_in[6];
    const float* b_lin = (const float*)d_in[7];
    float* out = (float*)d_out;

    fused<<<NBLK, 256>>>(spec, Wq, Wk, Wv, rel_t, rel_f, W_lin, b_lin,
                         out, out + FRAME_ELEMS);
}

// round 10
// speedup vs baseline: 1.1506x; 1.1506x over previous
#include <cuda_runtime.h>

#define Bc   4
#define Hc   512
#define Wc   229
#define Cc   32
#define OUTc 88
#define FRAME_ELEMS (Bc*Hc*OUTc)     /* 180224 */
#define NROW (Bc*Hc)                 /* 2048 */
#define NOT  6                       /* out tiles of 16 (88 -> 96 padded) */
#define WTIL (Wc*16)                 /* 3664 floats per out-tile */
#define PRTS 20                      /* partial row stride (floats) */

__device__ __align__(16) float g_ovT[Wc*NROW];      // ov transposed [w][row]
__device__ __align__(16) float g_w16[NOT*WTIL];     // weights [ot][w][16], pads zero-init

// ---------------------------------------------------------------------------
// fast exp(d), d <= 0 : FMA-pipe exp2 poly + magic-number round
// ---------------------------------------------------------------------------
__device__ __forceinline__ float fexp_neg(float d)
{
    const float L2E   = 1.4426950408889634f;
    const float MAGIC = 12582912.0f;              // 1.5 * 2^23
    float t0 = fmaf(d, L2E, MAGIC);
    float r  = t0 - MAGIC;
    float f  = fmaf(d, L2E, -r);                  // f in [-0.5, 0.5]
    float p = 1.3333558146e-3f;
    p = fmaf(p, f, 9.6181291076e-3f);
    p = fmaf(p, f, 5.5504108665e-2f);
    p = fmaf(p, f, 2.4022650696e-1f);
    p = fmaf(p, f, 6.9314718056e-1f);
    p = fmaf(p, f, 1.0f);
    int ri = __float_as_int(t0) - 0x4B400000;
    ri = ri < -126 ? -126 : ri;
    return p * __int_as_float((ri + 127) << 23);
}

// ---------------------------------------------------------------------------
// K1: one (b,h) row per block: 9-way softmax, attn out (smem-staged coalesced),
// ov written TRANSPOSED. Blocks 0..87 fold one WeffT column into g_w16.
// ---------------------------------------------------------------------------
__global__ void k1(const float* __restrict__ spec,
                   const float* __restrict__ Wq,  const float* __restrict__ Wk,
                   const float* __restrict__ Wv,  const float* __restrict__ rel_t,
                   const float* __restrict__ rel_f, const float* __restrict__ W_lin,
                   float* __restrict__ out_attn)
{
    int blk = blockIdx.x;
    int b = blk >> 9, h = blk & 511;
    __shared__ float sh[3][232];
    __shared__ float sh_attn[Wc*9];
    __shared__ float s_scal[7];
    int t = threadIdx.x;

    if (t < 7) {
        if (t == 0) {
            float a = 0.f;
            #pragma unroll
            for (int c = 0; c < Cc; c++) a = fmaf(Wq[c], Wk[c], a);
            s_scal[0] = a;
        } else if (t <= 3) {
            int kt = t - 1; float r = 0.f;
            #pragma unroll
            for (int c = 0; c < 16; c++) r = fmaf(Wq[c], rel_t[c*3 + kt], r);
            s_scal[t] = r;
        } else {
            int kf = t - 4; float r = 0.f;
            #pragma unroll
            for (int c = 0; c < 16; c++) r = fmaf(Wq[16 + c], rel_f[c*3 + kf], r);
            s_scal[t] = r;
        }
    }

    for (int i = t; i < 3*231; i += 256) {
        int row = i / 231, c = i % 231 - 1;
        int gh = h - 1 + row;
        float v = 0.f;
        if (gh >= 0 && gh < Hc && c >= 0 && c < Wc)
            v = spec[(b*Hc + gh)*Wc + c];
        sh[row][i % 231] = v;
    }
    __syncthreads();

    if (t < Wc) {
        const float A = s_scal[0];
        const float Rt[3] = { s_scal[1], s_scal[2], s_scal[3] };
        const float Rf[3] = { s_scal[4], s_scal[5], s_scal[6] };

        float s  = sh[1][t + 1];
        float sA = s * A;
        float nb[9], e[9];
        #pragma unroll
        for (int kt = 0; kt < 3; kt++) {
            float sr = s * Rt[kt];
            #pragma unroll
            for (int kf = 0; kf < 3; kf++) {
                float n = sh[kt][t + kf];
                nb[kt*3 + kf] = n;
                e[kt*3 + kf]  = fmaf(sA, n, fmaf(s, Rf[kf], sr));
            }
        }

        float m = e[0];
        #pragma unroll
        for (int k = 1; k < 9; k++) m = fmaxf(m, e[k]);

        float p[9], sum = 0.f;
        #pragma unroll
        for (int k = 0; k < 9; k++) { p[k] = fexp_neg(e[k] - m); sum += p[k]; }
        float rinv = __fdividef(1.f, sum);

        float ov = 0.f;
        #pragma unroll
        for (int k = 0; k < 9; k++) {
            float a = p[k] * rinv;
            sh_attn[t*9 + k] = a;
            ov = fmaf(a, nb[k], ov);
        }
        g_ovT[t*NROW + blk] = ov;            // transposed scatter (cheap: 15MB L2)
    }
    __syncthreads();

    float* dst = out_attn + blk*(Wc*9);
    for (int i = t; i < Wc*9; i += 256)      // coalesced attn writeback
        dst[i] = sh_attn[i];

    if (blk < OUTc && t < Wc) {              // fold one Weff column -> g_w16
        const float* base = W_lin + blk*(Cc*Wc) + t;
        float acc = 0.f;
        #pragma unroll
        for (int c = 0; c < Cc; c++)
            acc = fmaf(base[c*Wc], Wv[c], acc);
        g_w16[(blk >> 4)*WTIL + t*16 + (blk & 15)] = acc;
    }
}

// ---------------------------------------------------------------------------
// K2: frame = sigmoid(ov @ Weff^T + b)
// grid (6 outTiles, 64 rowChunks) x 256 thr. Block: 32 rows x 16 outs.
// thread = (lane=row, ks=K-chunk of ~29). Per w: 1 coalesced LDG (ovT) +
// 4 broadcast LDS (weights) -> 16 FMA. Weight tile 14.6KB smem.
// ---------------------------------------------------------------------------
__global__ void __launch_bounds__(256)
k2(const float* __restrict__ b_lin, float* __restrict__ out_frame)
{
    __shared__ __align__(16) float s_w[WTIL];           // 14.6 KB
    __shared__ __align__(16) float s_prt[7*32*PRTS];    // 17.9 KB

    int t  = threadIdx.x;
    int ot = blockIdx.x;                     // out tile 0..5
    int rc = blockIdx.y;                     // row chunk 0..63

    {   // weight tile fill: contiguous float4 both sides
        const float4* src = (const float4*)(g_w16 + ot*WTIL);
        for (int i = t; i < WTIL/4; i += 256)
            ((float4*)s_w)[i] = src[i];
    }
    __syncthreads();

    int lane = t & 31;
    int ks   = t >> 5;                       // 0..7
    int row  = rc*32 + lane;
    int w0 = (ks * Wc) >> 3;
    int w1 = ((ks + 1) * Wc) >> 3;

    const float* ovcol = g_ovT + row;

    float4 a0 = {0,0,0,0}, a1 = {0,0,0,0}, a2 = {0,0,0,0}, a3 = {0,0,0,0};

    int w = w0;
    for (; w + 2 <= w1; w += 2) {
        float  v0  = __ldg(ovcol + (w  )*NROW);
        float  v1  = __ldg(ovcol + (w+1)*NROW);
        const float* wp0 = s_w + (w  )*16;
        const float* wp1 = s_w + (w+1)*16;
        float4 w00 = *(const float4*)(wp0     );
        float4 w01 = *(const float4*)(wp0 +  4);
        float4 w02 = *(const float4*)(wp0 +  8);
        float4 w03 = *(const float4*)(wp0 + 12);
        float4 w10 = *(const float4*)(wp1     );
        float4 w11 = *(const float4*)(wp1 +  4);
        float4 w12 = *(const float4*)(wp1 +  8);
        float4 w13 = *(const float4*)(wp1 + 12);

        a0.x = fmaf(v0, w00.x, a0.x); a0.y = fmaf(v0, w00.y, a0.y);
        a0.z = fmaf(v0, w00.z, a0.z); a0.w = fmaf(v0, w00.w, a0.w);
        a1.x = fmaf(v0, w01.x, a1.x); a1.y = fmaf(v0, w01.y, a1.y);
        a1.z = fmaf(v0, w01.z, a1.z); a1.w = fmaf(v0, w01.w, a1.w);
        a2.x = fmaf(v0, w02.x, a2.x); a2.y = fmaf(v0, w02.y, a2.y);
        a2.z = fmaf(v0, w02.z, a2.z); a2.w = fmaf(v0, w02.w, a2.w);
        a3.x = fmaf(v0, w03.x, a3.x); a3.y = fmaf(v0, w03.y, a3.y);
        a3.z = fmaf(v0, w03.z, a3.z); a3.w = fmaf(v0, w03.w, a3.w);

        a0.x = fmaf(v1, w10.x, a0.x); a0.y = fmaf(v1, w10.y, a0.y);
        a0.z = fmaf(v1, w10.z, a0.z); a0.w = fmaf(v1, w10.w, a0.w);
        a1.x = fmaf(v1, w11.x, a1.x); a1.y = fmaf(v1, w11.y, a1.y);
        a1.z = fmaf(v1, w11.z, a1.z); a1.w = fmaf(v1, w11.w, a1.w);
        a2.x = fmaf(v1, w12.x, a2.x); a2.y = fmaf(v1, w12.y, a2.y);
        a2.z = fmaf(v1, w12.z, a2.z); a2.w = fmaf(v1, w12.w, a2.w);
        a3.x = fmaf(v1, w13.x, a3.x); a3.y = fmaf(v1, w13.y, a3.y);
        a3.z = fmaf(v1, w13.z, a3.z); a3.w = fmaf(v1, w13.w, a3.w);
    }
    for (; w < w1; w++) {
        float v = __ldg(ovcol + w*NROW);
        const float* wp = s_w + w*16;
        float4 q0 = *(const float4*)(wp     );
        float4 q1 = *(const float4*)(wp +  4);
        float4 q2 = *(const float4*)(wp +  8);
        float4 q3 = *(const float4*)(wp + 12);
        a0.x = fmaf(v, q0.x, a0.x); a0.y = fmaf(v, q0.y, a0.y);
        a0.z = fmaf(v, q0.z, a0.z); a0.w = fmaf(v, q0.w, a0.w);
        a1.x = fmaf(v, q1.x, a1.x); a1.y = fmaf(v, q1.y, a1.y);
        a1.z = fmaf(v, q1.z, a1.z); a1.w = fmaf(v, q1.w, a1.w);
        a2.x = fmaf(v, q2.x, a2.x); a2.y = fmaf(v, q2.y, a2.y);
        a2.z = fmaf(v, q2.z, a2.z); a2.w = fmaf(v, q2.w, a2.w);
        a3.x = fmaf(v, q3.x, a3.x); a3.y = fmaf(v, q3.y, a3.y);
        a3.z = fmaf(v, q3.z, a3.z); a3.w = fmaf(v, q3.w, a3.w);
    }

    if (ks > 0) {                            // publish partials
        float* pp = s_prt + ((ks - 1)*32 + lane)*PRTS;
        *(float4*)(pp     ) = a0;  *(float4*)(pp +  4) = a1;
        *(float4*)(pp +  8) = a2;  *(float4*)(pp + 12) = a3;
    }
    __syncthreads();

    if (t < 32) {                            // warp 0: reduce + epilogue
        #pragma unroll
        for (int s = 0; s < 7; s++) {
            const float* pp = s_prt + (s*32 + lane)*PRTS;
            float4 p0 = *(const float4*)(pp);
            float4 p1 = *(const float4*)(pp + 4);
            float4 p2 = *(const float4*)(pp + 8);
            float4 p3 = *(const float4*)(pp + 12);
            a0.x += p0.x; a0.y += p0.y; a0.z += p0.z; a0.w += p0.w;
            a1.x += p1.x; a1.y += p1.y; a1.z += p1.z; a1.w += p1.w;
            a2.x += p2.x; a2.y += p2.y; a2.z += p2.z; a2.w += p2.w;
            a3.x += p3.x; a3.y += p3.y; a3.z += p3.z; a3.w += p3.w;
        }

        int o0 = ot*16;
        float4 accs[4] = {a0, a1, a2, a3};
        #pragma unroll
        for (int g = 0; g < 4; g++) {
            int o = o0 + g*4;
            if (o < OUTc) {                  // 88 % 16 == 8: groups fully in/out
                float4 bb = *(const float4*)&b_lin[o];
                float4 rr;
                rr.x = __fdividef(1.f, 1.f + __expf(-(accs[g].x + bb.x)));
                rr.y = __fdividef(1.f, 1.f + __expf(-(accs[g].y + bb.y)));
                rr.z = __fdividef(1.f, 1.f + __expf(-(accs[g].z + bb.z)));
                rr.w = __fdividef(1.f, 1.f + __expf(-(accs[g].w + bb.w)));
                *(float4*)&out_frame[row*OUTc + o] = rr;
            }
        }
    }
}

// ---------------------------------------------------------------------------
extern "C" void kernel_launch(void* const* d_in, const int* in_sizes, int n_in,
                              void* d_out, int out_size)
{
    const float* spec  = (const float*)d_in[0];
    const float* Wq    = (const float*)d_in[1];
    const float* Wk    = (const float*)d_in[2];
    const float* Wv    = (const float*)d_in[3];
    const float* rel_t = (const float*)d_in[4];
    const float* rel_f = (const float*)d_in[5];
    const float* W_lin = (const float*)d_in[6];
    const float* b_lin = (const float*)d_in[7];
    float* out = (float*)d_out;

    k1<<<NROW, 256>>>(spec, Wq, Wk, Wv, rel_t, rel_f, W_lin, out + FRAME_ELEMS);
    dim3 g2(NOT, NROW/32);
    k2<<<g2, 256>>>(b_lin, out);
}